// round 2
// baseline (speedup 1.0000x reference)
#include <cuda_runtime.h>

// ---------------------------------------------------------------------------
// MultiScaleRoIAlign (torchvision semantics, aligned=False, sampling_ratio=2)
// feats: [2,256,{200,100,50,25}^2] fp32 NCHW; boxes [2,256,4]; out [512,256,7,7]
//
// Pass 1: one fused kernel transposes all levels NCHW -> NHWC scratch.
// Pass 2: one block per ROI; items = (bin, float4-channel-group) so each
//         bilinear tap is a coalesced 512B load per warp; output staged in
//         shared memory ([C][7*7] layout) and written contiguously as float4.
// ---------------------------------------------------------------------------

#define NCH 256

// NHWC scratch: 2*256*(200^2+100^2+50^2+25^2) = 27,200,000 floats
__device__ float4 g_nhwc4[6800000];

// float-element offsets of each level inside scratch
#define OFF0 0
#define OFF1 20480000
#define OFF2 25600000
#define OFF3 26880000

// block ranges for fused transpose (bx * H * 16 blocks per level)
#define T0_END 22400   //  7*200*16
#define T1_END 28800   // +4*100*16
#define T2_END 30400   // +2* 50*16
#define T3_END 30800   // +1* 25*16

__global__ void transpose_all(const float* __restrict__ f0,
                              const float* __restrict__ f1,
                              const float* __restrict__ f2,
                              const float* __restrict__ f3)
{
    __shared__ float tile[32][33];
    int bid = blockIdx.x;

    const float* in; int H, bx, base, off;
    if (bid < T0_END)      { in = f0; H = 200; bx = 7; base = 0;      off = OFF0; }
    else if (bid < T1_END) { in = f1; H = 100; bx = 4; base = T0_END; off = OFF1; }
    else if (bid < T2_END) { in = f2; H = 50;  bx = 2; base = T1_END; off = OFF2; }
    else                   { in = f3; H = 25;  bx = 1; base = T2_END; off = OFF3; }

    int rel = bid - base;
    int xt  = rel % bx;
    int y   = (rel / bx) % H;
    int zc  = rel / (bx * H);          // 0..15  (batch*8 + channel-tile)
    int b   = zc >> 3;
    int c0  = (zc & 7) * 32;

    float* outp = reinterpret_cast<float*>(g_nhwc4) + off;

    int x = xt * 32 + threadIdx.x;
    if (x < H) {
        size_t idx = ((size_t)(b * NCH + c0 + threadIdx.y) * H + y) * H + x;
        tile[threadIdx.y][threadIdx.x] = in[idx];
    }
    __syncthreads();

    int xo = xt * 32 + threadIdx.y;
    if (xo < H) {
        size_t idx = (((size_t)b * H + y) * H + xo) * NCH + c0 + threadIdx.x;
        outp[idx] = tile[threadIdx.x][threadIdx.y];
    }
}

__global__ void __launch_bounds__(256)
roi_align_kernel(const float* __restrict__ boxes, float* __restrict__ out)
{
    // [128 channels][49 bins] staging per phase = 25088 bytes
    __shared__ float s_out[128 * 49];

    int n = blockIdx.x;                       // roi index 0..511
    float4 bx = __ldg(reinterpret_cast<const float4*>(boxes) + n);
    int b = n >> 8;                           // batch index

    // LevelMapper: floor(4 + log2(sqrt(w*h)/224) + 1e-6), clip [2,5], -2
    float s = sqrtf((bx.z - bx.x) * (bx.w - bx.y));
    int lvl = (int)floorf(4.0f + log2f(s * (1.0f / 224.0f)) + 1e-6f);
    lvl = min(max(lvl, 2), 5) - 2;

    int H;  float sc;  int off4;              // off4 in float4 units
    switch (lvl) {
        case 0:  H = 200; sc = 0.25f;    off4 = OFF0 / 4; break;
        case 1:  H = 100; sc = 0.125f;   off4 = OFF1 / 4; break;
        case 2:  H = 50;  sc = 0.0625f;  off4 = OFF2 / 4; break;
        default: H = 25;  sc = 0.03125f; off4 = OFF3 / 4; break;
    }
    const float4* f4 = g_nhwc4 + off4 + (size_t)b * H * H * (NCH / 4);

    float x1s = bx.x * sc, y1s = bx.y * sc;
    float x2s = bx.z * sc, y2s = bx.w * sc;
    float binw = fmaxf(x2s - x1s, 1.0f) * (1.0f / 7.0f);
    float binh = fmaxf(y2s - y1s, 1.0f) * (1.0f / 7.0f);
    float fH = (float)H;

    // two phases of 128 channels (32 float4-groups) each
    #pragma unroll 1
    for (int p = 0; p < 2; p++) {
        // items: 49 bins * 32 cg = 1568
        for (int item = threadIdx.x; item < 49 * 32; item += 256) {
            int bin = item >> 5;
            int cgl = item & 31;
            int cg  = p * 32 + cgl;           // global float4 channel group
            int oy  = bin / 7;
            int ox  = bin - oy * 7;

            float4 acc = make_float4(0.f, 0.f, 0.f, 0.f);

            #pragma unroll
            for (int iy = 0; iy < 2; iy++) {
                float yy = y1s + ((float)oy + 0.25f + 0.5f * (float)iy) * binh;
                if (yy <= -1.0f || yy >= fH) continue;   // invalid sample -> 0
                float yc = fmaxf(yy, 0.0f);
                int yl = min((int)yc, H - 1);
                int yh = min(yl + 1, H - 1);
                float ly = (yl >= H - 1) ? 0.0f : (yc - (float)yl);
                float hy = 1.0f - ly;

                #pragma unroll
                for (int ix = 0; ix < 2; ix++) {
                    float xx = x1s + ((float)ox + 0.25f + 0.5f * (float)ix) * binw;
                    if (xx <= -1.0f || xx >= fH) continue;
                    float xc = fmaxf(xx, 0.0f);
                    int xl = min((int)xc, H - 1);
                    int xh = min(xl + 1, H - 1);
                    float lx = (xl >= H - 1) ? 0.0f : (xc - (float)xl);
                    float hx = 1.0f - lx;

                    float w00 = hy * hx, w01 = hy * lx;
                    float w10 = ly * hx, w11 = ly * lx;

                    const float4 v00 = __ldg(&f4[((size_t)yl * H + xl) * 64 + cg]);
                    const float4 v01 = __ldg(&f4[((size_t)yl * H + xh) * 64 + cg]);
                    const float4 v10 = __ldg(&f4[((size_t)yh * H + xl) * 64 + cg]);
                    const float4 v11 = __ldg(&f4[((size_t)yh * H + xh) * 64 + cg]);

                    acc.x += w00 * v00.x + w01 * v01.x + w10 * v10.x + w11 * v11.x;
                    acc.y += w00 * v00.y + w01 * v01.y + w10 * v10.y + w11 * v11.y;
                    acc.z += w00 * v00.z + w01 * v01.z + w10 * v10.z + w11 * v11.z;
                    acc.w += w00 * v00.w + w01 * v01.w + w10 * v10.w + w11 * v11.w;
                }
            }

            int cl = cgl * 4;                 // local channel within phase
            s_out[(cl + 0) * 49 + bin] = acc.x * 0.25f;
            s_out[(cl + 1) * 49 + bin] = acc.y * 0.25f;
            s_out[(cl + 2) * 49 + bin] = acc.z * 0.25f;
            s_out[(cl + 3) * 49 + bin] = acc.w * 0.25f;
        }
        __syncthreads();

        // contiguous float4 write of 128*49 floats for this phase
        float4* o4 = reinterpret_cast<float4*>(out + (size_t)n * (NCH * 49)
                                               + p * (128 * 49));
        const float4* s4 = reinterpret_cast<const float4*>(s_out);
        for (int i = threadIdx.x; i < 128 * 49 / 4; i += 256)
            o4[i] = s4[i];
        __syncthreads();
    }
}

extern "C" void kernel_launch(void* const* d_in, const int* in_sizes, int n_in,
                              void* d_out, int out_size)
{
    const float* f0 = (const float*)d_in[0];
    const float* f1 = (const float*)d_in[1];
    const float* f2 = (const float*)d_in[2];
    const float* f3 = (const float*)d_in[3];
    const float* boxes = (const float*)d_in[4];
    float* out = (float*)d_out;

    transpose_all<<<T3_END, dim3(32, 32)>>>(f0, f1, f2, f3);
    roi_align_kernel<<<512, 256>>>(boxes, out);
}